// round 2
// baseline (speedup 1.0000x reference)
#include <cuda_runtime.h>

#define EPSV 1e-5f
#define NMAX 100000
#define EMAX 1600000

// ---------------- scratch (device globals; no allocation allowed) -------------
// alignas(16): float4 loads and red.global.add.v4.f32 require 16B alignment;
// bare __device__ float arrays are only guaranteed element alignment.
__device__ alignas(16) float  d_h  [NMAX * 16];
__device__ alignas(16) float  d_xl [NMAX * 32];
__device__ alignas(16) float  d_xr [NMAX * 32];
__device__ alignas(16) float  d_g  [NMAX * 32];
__device__ alignas(16) float  d_u  [NMAX * 16];
__device__ float  d_den[NMAX * 2];
__device__ int    d_src[EMAX];
__device__ int    d_dst[EMAX];
__device__ double d_stats[4];   // [0],[1]: sum/sumsq of g (norm1); [2],[3]: of u (norm2)
__device__ int    d_is64;       // 1 if edge_index buffer is int64, 0 if int32

// ---------------- helpers ----------------
__device__ __forceinline__ float leaky(float v) { return v > 0.f ? v : 0.2f * v; }

// Block-wide reduction of (s,q) into two double accumulators. blockDim.x == 256.
__device__ __forceinline__ void blockReduceAdd2(float s, float q, double* o0, double* o1) {
    __shared__ float rs[8], rq[8];
#pragma unroll
    for (int o = 16; o; o >>= 1) {
        s += __shfl_xor_sync(0xffffffffu, s, o);
        q += __shfl_xor_sync(0xffffffffu, q, o);
    }
    int w = threadIdx.x >> 5, l = threadIdx.x & 31;
    if (l == 0) { rs[w] = s; rq[w] = q; }
    __syncthreads();
    if (w == 0) {
        s = (l < 8) ? rs[l] : 0.f;
        q = (l < 8) ? rq[l] : 0.f;
#pragma unroll
        for (int o = 4; o; o >>= 1) {
            s += __shfl_xor_sync(0xffffffffu, s, o);
            q += __shfl_xor_sync(0xffffffffu, q, o);
        }
        if (l == 0) { atomicAdd(o0, (double)s); atomicAdd(o1, (double)q); }
    }
}

// ------------- K_detect: is the edge_index buffer int64 or int32? -------------
// If int64 (little endian, values < 2^31), every odd int32 word is 0.
// 256 random-valued odd words all being zero under int32 has prob ~0.
__global__ void k_detect(const int* __restrict__ ei32, int E2) {
    __shared__ int allzero;
    if (threadIdx.x == 0) allzero = 1;
    __syncthreads();
    long long idx = 2LL * threadIdx.x + 1;
    if (idx < E2 && ei32[idx] != 0) allzero = 0;   // benign race
    __syncthreads();
    if (threadIdx.x == 0) d_is64 = allzero;
}

// ---------------- K_conv: edge_index -> int32 src/dst ----------------
__global__ void __launch_bounds__(256) k_conv(const int* __restrict__ ei32, int E) {
    int i = blockIdx.x * 256 + threadIdx.x;
    if (i >= E) return;
    if (d_is64) {
        const long long* e64 = (const long long*)ei32;
        d_src[i] = (int)e64[i];
        d_dst[i] = (int)e64[E + i];
    } else {
        d_src[i] = ei32[i];
        d_dst[i] = ei32[E + i];
    }
}

// ---------------- K_embed: h = relu(node_LN(x @ W + b)); out = h ----------------
// 32 nodes per block of 256 threads.
__global__ void __launch_bounds__(256) k_embed(
    const float* __restrict__ x, const float* __restrict__ W,
    const float* __restrict__ b, const float* __restrict__ lnw,
    const float* __restrict__ lnb, float* __restrict__ out, int N)
{
    __shared__ float sx[32][129];
    __shared__ float sW[2048];
    __shared__ float sy[32][17];
    int t = threadIdx.x;
    int n0 = blockIdx.x * 32;
    for (int i = t; i < 2048; i += 256) sW[i] = W[i];
    for (int i = t; i < 4096; i += 256) {
        int n = i >> 7, k = i & 127;
        int gn = n0 + n;
        sx[n][k] = (gn < N) ? x[gn * 128 + k] : 0.f;
    }
    __syncthreads();
    {
        int n1 = t >> 4, n2 = 16 + (t >> 4), c = t & 15;
        float a1 = b[c], a2 = a1;
#pragma unroll 16
        for (int k = 0; k < 128; k++) {
            float wv = sW[k * 16 + c];
            a1 += sx[n1][k] * wv;
            a2 += sx[n2][k] * wv;
        }
        sy[n1][c] = a1;
        sy[n2][c] = a2;
    }
    __syncthreads();
    if (t < 32) {
        int gn = n0 + t;
        if (gn < N) {
            float mu = 0.f;
#pragma unroll
            for (int c = 0; c < 16; c++) mu += sy[t][c];
            mu *= (1.f / 16.f);
            float var = 0.f;
#pragma unroll
            for (int c = 0; c < 16; c++) { float d = sy[t][c] - mu; var += d * d; }
            var *= (1.f / 16.f);
            float inv = rsqrtf(var + EPSV);
#pragma unroll
            for (int c = 0; c < 16; c++) {
                float v = fmaxf((sy[t][c] - mu) * inv * lnw[c] + lnb[c], 0.f);
                d_h[gn * 16 + c] = v;
                out[gn * 16 + c] = v;
            }
        }
    }
}

// ---------------- K_transform: xl = h@Wl+bl, xr = h@Wr+br; zero g/den/stats ----
// 64 nodes per block of 256 threads.
__global__ void __launch_bounds__(256) k_transform(
    const float* __restrict__ Wl, const float* __restrict__ bl,
    const float* __restrict__ Wr, const float* __restrict__ br, int N)
{
    __shared__ float sh[64][17];
    __shared__ float sWl[512], sWr[512];
    __shared__ float sbl[32], sbr[32];
    int t = threadIdx.x;
    int n0 = blockIdx.x * 64;
    for (int i = t; i < 512; i += 256) { sWl[i] = Wl[i]; sWr[i] = Wr[i]; }
    if (t < 32) { sbl[t] = bl[t]; sbr[t] = br[t]; }
    for (int i = t; i < 1024; i += 256) {
        int n = i >> 4, k = i & 15;
        int gn = n0 + n;
        sh[n][k] = (gn < N) ? d_h[gn * 16 + k] : 0.f;
    }
    if (blockIdx.x == 0 && t < 4) d_stats[t] = 0.0;
    __syncthreads();
    int c = t & 31, w = t >> 5;
#pragma unroll
    for (int j = 0; j < 8; j++) {
        int nl = w * 8 + j;
        int gn = n0 + nl;
        if (gn >= N) break;   // warp-uniform (gn same across warp)
        float al = sbl[c], ar = sbr[c];
#pragma unroll
        for (int k = 0; k < 16; k++) {
            float hv = sh[nl][k];
            al += hv * sWl[k * 32 + c];
            ar += hv * sWr[k * 32 + c];
        }
        d_xl[gn * 32 + c] = al;
        d_xr[gn * 32 + c] = ar;
        d_g [gn * 32 + c] = 0.f;
    }
    if (t < 128) {
        int gn = n0 + (t >> 1);
        if (gn < N) d_den[gn * 2 + (t & 1)] = 0.f;
    }
}

// ---------------- K_edge: the heavy per-edge pass (8 lanes / edge) ----------------
__global__ void __launch_bounds__(256) k_edge(
    const float4* __restrict__ eattr,
    const float* __restrict__ We, const float* __restrict__ att, int E, int N)
{
    __shared__ float4 sWe[32];  // We[4][32] as float4
    __shared__ float4 sAtt[8];  // att[2][16] as 8 float4
    int t = threadIdx.x;
    if (t < 32) sWe[t] = ((const float4*)We)[t];
    else if (t < 40) sAtt[t - 32] = ((const float4*)att)[t - 32];
    __syncthreads();

    int lane = t & 7;
    int head = lane >> 2;
    unsigned smask = 0xFu << ((t & 31) & ~3);  // 4-lane subgroup (one head of one edge)
    int e = (blockIdx.x * 256 + t) >> 3;
    if (e >= E) return;

    // clamp defensively: a bad decode shows up as rel_err, not a crash
    int s = min(max(d_src[e], 0), N - 1);
    int d = min(max(d_dst[e], 0), N - 1);
    const float4* xl4 = (const float4*)d_xl;
    const float4* xr4 = (const float4*)d_xr;
    float4 a  = xl4[s * 8 + lane];
    float4 bb = xr4[d * 8 + lane];
    float4 ea = eattr[e];
    float4 w0 = sWe[lane], w1 = sWe[8 + lane], w2 = sWe[16 + lane], w3 = sWe[24 + lane];

    float mx = a.x + bb.x + ea.x * w0.x + ea.y * w1.x + ea.z * w2.x + ea.w * w3.x;
    float my = a.y + bb.y + ea.x * w0.y + ea.y * w1.y + ea.z * w2.y + ea.w * w3.y;
    float mz = a.z + bb.z + ea.x * w0.z + ea.y * w1.z + ea.z * w2.z + ea.w * w3.z;
    float mw = a.w + bb.w + ea.x * w0.w + ea.y * w1.w + ea.z * w2.w + ea.w * w3.w;
    mx = leaky(mx); my = leaky(my); mz = leaky(mz); mw = leaky(mw);

    float4 at = sAtt[lane];
    float p = mx * at.x + my * at.y + mz * at.z + mw * at.w;
    p += __shfl_xor_sync(smask, p, 1);
    p += __shfl_xor_sync(smask, p, 2);
    float ex = __expf(p);   // shift-free softmax: alpha invariant to max subtraction

    if ((lane & 3) == 0) atomicAdd(&d_den[d * 2 + head], ex);

    unsigned long long gp = (unsigned long long)__cvta_generic_to_global(&d_g[d * 32 + lane * 4]);
    asm volatile("red.global.add.v4.f32 [%0], {%1,%2,%3,%4};"
                 :: "l"(gp), "f"(ex * a.x), "f"(ex * a.y), "f"(ex * a.z), "f"(ex * a.w)
                 : "memory");
}

// ------- K_final: self-loop + normalize by den + gat_b; accumulate norm1 stats ---
__global__ void __launch_bounds__(256) k_final(
    const float* __restrict__ att, const float* __restrict__ gatb, int N)
{
    __shared__ float4 sAtt[8];
    int t = threadIdx.x;
    if (t < 8) sAtt[t] = ((const float4*)att)[t];
    __syncthreads();

    int lane = t & 7;
    int head = lane >> 2;
    unsigned smask = 0xFu << ((t & 31) & ~3);
    int n = (blockIdx.x * 256 + t) >> 3;

    float s_loc = 0.f, q_loc = 0.f;
    if (n < N) {
        const float4* xl4 = (const float4*)d_xl;
        const float4* xr4 = (const float4*)d_xr;
        float4 a  = xl4[n * 8 + lane];
        float4 bb = xr4[n * 8 + lane];
        float mx = leaky(a.x + bb.x);
        float my = leaky(a.y + bb.y);
        float mz = leaky(a.z + bb.z);
        float mw = leaky(a.w + bb.w);
        float4 at = sAtt[lane];
        float p = mx * at.x + my * at.y + mz * at.z + mw * at.w;
        p += __shfl_xor_sync(smask, p, 1);
        p += __shfl_xor_sync(smask, p, 2);
        float ex = __expf(p);
        float inv = 1.f / (d_den[n * 2 + head] + ex);
        float4 g  = ((const float4*)d_g)[n * 8 + lane];
        float4 gb = ((const float4*)gatb)[lane];
        float rx = (g.x + ex * a.x) * inv + gb.x;
        float ry = (g.y + ex * a.y) * inv + gb.y;
        float rz = (g.z + ex * a.z) * inv + gb.z;
        float rw = (g.w + ex * a.w) * inv + gb.w;
        ((float4*)d_g)[n * 8 + lane] = make_float4(rx, ry, rz, rw);
        s_loc = rx + ry + rz + rw;
        q_loc = rx * rx + ry * ry + rz * rz + rw * rw;
    }
    blockReduceAdd2(s_loc, q_loc, &d_stats[0], &d_stats[1]);
}

// ------- K_lin: graph_LN(g)+relu, u = t @ linW + linb; accumulate norm2 stats ----
// 16 nodes per block of 256 threads.
__global__ void __launch_bounds__(256) k_lin(
    const float* __restrict__ n1w, const float* __restrict__ n1b,
    const float* __restrict__ linW, const float* __restrict__ linb, int N)
{
    __shared__ float st[16][33];
    __shared__ float sW[512];
    __shared__ float sb[16];
    int t = threadIdx.x;
    int n0 = blockIdx.x * 16;
    for (int i = t; i < 512; i += 256) sW[i] = linW[i];
    if (t < 16) sb[t] = linb[t];

    double mu_d  = d_stats[0] / (32.0 * N);
    double var_d = d_stats[1] / (32.0 * N) - mu_d * mu_d;
    float mu  = (float)mu_d;
    float inv = rsqrtf((float)var_d + EPSV);

#pragma unroll
    for (int r = 0; r < 2; r++) {
        int i = t + r * 256;
        int nl = i >> 5, k = i & 31;
        int gn = n0 + nl;
        float v = 0.f;
        if (gn < N) {
            v = (d_g[gn * 32 + k] - mu) * inv * n1w[k] + n1b[k];
            v = fmaxf(v, 0.f);
        }
        st[nl][k] = v;
    }
    __syncthreads();

    int nl = t >> 4, c = t & 15;
    int gn = n0 + nl;
    float s_loc = 0.f, q_loc = 0.f;
    if (gn < N) {
        float acc = sb[c];
#pragma unroll
        for (int k = 0; k < 32; k++) acc += st[nl][k] * sW[k * 16 + c];
        d_u[gn * 16 + c] = acc;
        s_loc = acc;
        q_loc = acc * acc;
    }
    blockReduceAdd2(s_loc, q_loc, &d_stats[2], &d_stats[3]);
}

// ------- K_resid: graph_LN(u), residual+relu -> new h; out = max(out, h) ---------
__global__ void __launch_bounds__(256) k_resid(
    const float* __restrict__ n2w, const float* __restrict__ n2b,
    float* __restrict__ out, int N)
{
    int i = blockIdx.x * 256 + threadIdx.x;
    if (i >= N * 16) return;
    int c = i & 15;
    double mu_d  = d_stats[2] / (16.0 * N);
    double var_d = d_stats[3] / (16.0 * N) - mu_d * mu_d;
    float mu  = (float)mu_d;
    float inv = rsqrtf((float)var_d + EPSV);
    float v  = (d_u[i] - mu) * inv * n2w[c] + n2b[c];
    float hn = fmaxf(v + d_h[i], 0.f);
    d_h[i] = hn;
    out[i] = fmaxf(out[i], hn);
}

// ---------------- launch ----------------
extern "C" void kernel_launch(void* const* d_in, const int* in_sizes, int n_in,
                              void* d_out, int out_size)
{
    const float* x     = (const float*)d_in[0];
    const int*   ei32  = (const int*)d_in[1];      // int32 OR int64 (detected on device)
    const float* eattr = (const float*)d_in[2];
    const float* embW  = (const float*)d_in[3];
    const float* embB  = (const float*)d_in[4];
    const float* ln0w  = (const float*)d_in[5];
    const float* ln0b  = (const float*)d_in[6];
    const float* Wl    = (const float*)d_in[7];
    const float* bl    = (const float*)d_in[8];
    const float* Wr    = (const float*)d_in[9];
    const float* br    = (const float*)d_in[10];
    const float* We    = (const float*)d_in[11];
    const float* att   = (const float*)d_in[12];
    const float* gatb  = (const float*)d_in[13];
    const float* n1w   = (const float*)d_in[14];
    const float* n1b   = (const float*)d_in[15];
    const float* linW  = (const float*)d_in[16];
    const float* linb  = (const float*)d_in[17];
    const float* n2w   = (const float*)d_in[18];
    const float* n2b   = (const float*)d_in[19];
    float* out = (float*)d_out;

    int N = in_sizes[0] / 128;
    int E = in_sizes[1] / 2;

    k_detect<<<1, 256>>>(ei32, in_sizes[1]);
    k_conv <<<(E + 255) / 256, 256>>>(ei32, E);
    k_embed<<<(N + 31) / 32, 256>>>(x, embW, embB, ln0w, ln0b, out, N);

    for (int l = 0; l < 2; l++) {
        k_transform<<<(N + 63) / 64, 256>>>(Wl + l * 512, bl + l * 32,
                                            Wr + l * 512, br + l * 32, N);
        k_edge <<<(E * 8 + 255) / 256, 256>>>((const float4*)eattr,
                                              We + l * 128, att + l * 32, E, N);
        k_final<<<(N * 8 + 255) / 256, 256>>>(att + l * 32, gatb + l * 32, N);
        k_lin  <<<(N + 15) / 16, 256>>>(n1w + l * 32, n1b + l * 32,
                                        linW + l * 512, linb + l * 16, N);
        k_resid<<<(N * 16 + 255) / 256, 256>>>(n2w + l * 16, n2b + l * 16, out, N);
    }
}

// round 3
// speedup vs baseline: 1.0181x; 1.0181x over previous
#include <cuda_runtime.h>

#define EPSV 1e-5f
#define NMAX 100000
#define EMAX 1600000
#define EDGE_CHUNKS 4

// ---------------- scratch (device globals; no allocation allowed) -------------
__device__ alignas(16) float  d_h  [NMAX * 16];
__device__ alignas(16) float  d_xl [NMAX * 32];
__device__ alignas(16) float  d_xr [NMAX * 32];
__device__ alignas(16) float  d_g  [NMAX * 32];
__device__ alignas(16) float  d_u  [NMAX * 16];
__device__ float  d_den[NMAX * 2];
__device__ int    d_src[EMAX];
__device__ int    d_dst[EMAX];
__device__ double d_stats[4];   // [0],[1]: sum/sumsq of g (norm1); [2],[3]: of u (norm2)
__device__ int    d_is64;       // 1 if edge_index buffer is int64, 0 if int32

// ---------------- helpers ----------------
__device__ __forceinline__ float leaky(float v) { return v > 0.f ? v : 0.2f * v; }

__device__ __forceinline__ void blockReduceAdd2(float s, float q, double* o0, double* o1) {
    __shared__ float rs[8], rq[8];
#pragma unroll
    for (int o = 16; o; o >>= 1) {
        s += __shfl_xor_sync(0xffffffffu, s, o);
        q += __shfl_xor_sync(0xffffffffu, q, o);
    }
    int w = threadIdx.x >> 5, l = threadIdx.x & 31;
    if (l == 0) { rs[w] = s; rq[w] = q; }
    __syncthreads();
    if (w == 0) {
        s = (l < 8) ? rs[l] : 0.f;
        q = (l < 8) ? rq[l] : 0.f;
#pragma unroll
        for (int o = 4; o; o >>= 1) {
            s += __shfl_xor_sync(0xffffffffu, s, o);
            q += __shfl_xor_sync(0xffffffffu, q, o);
        }
        if (l == 0) { atomicAdd(o0, (double)s); atomicAdd(o1, (double)q); }
    }
}

// ------------- K_detect: is the edge_index buffer int64 or int32? -------------
__global__ void k_detect(const int* __restrict__ ei32, int E2) {
    __shared__ int allzero;
    if (threadIdx.x == 0) allzero = 1;
    __syncthreads();
    long long idx = 2LL * threadIdx.x + 1;
    if (idx < E2 && ei32[idx] != 0) allzero = 0;   // benign race
    __syncthreads();
    if (threadIdx.x == 0) d_is64 = allzero;
}

// ---------------- K_conv: edge_index -> int32 src/dst ----------------
__global__ void __launch_bounds__(256) k_conv(const int* __restrict__ ei32, int E) {
    int i = blockIdx.x * 256 + threadIdx.x;
    if (i >= E) return;
    if (d_is64) {
        const long long* e64 = (const long long*)ei32;
        d_src[i] = (int)__ldcs(&e64[i]);
        d_dst[i] = (int)__ldcs(&e64[E + i]);
    } else {
        d_src[i] = __ldcs(&ei32[i]);
        d_dst[i] = __ldcs(&ei32[E + i]);
    }
}

// ------- K_embed_tf: h = relu(node_LN(x@W+b)); out=h; xl/xr = h@Wl/Wr; zero g,den -
// 32 nodes per block of 256 threads.
__global__ void __launch_bounds__(256) k_embed_tf(
    const float* __restrict__ x, const float* __restrict__ W,
    const float* __restrict__ b, const float* __restrict__ lnw,
    const float* __restrict__ lnb,
    const float* __restrict__ Wl, const float* __restrict__ bl,
    const float* __restrict__ Wr, const float* __restrict__ br,
    float* __restrict__ out, int N)
{
    __shared__ float sx[32][129];
    __shared__ float sW[2048];
    __shared__ float sy[32][17];
    __shared__ float sWl[512], sWr[512], sbl[32], sbr[32];
    int t = threadIdx.x;
    int n0 = blockIdx.x * 32;
    for (int i = t; i < 2048; i += 256) sW[i] = W[i];
    for (int i = t; i < 512; i += 256) { sWl[i] = Wl[i]; sWr[i] = Wr[i]; }
    if (t < 32) { sbl[t] = bl[t]; sbr[t] = br[t]; }
    for (int i = t; i < 4096; i += 256) {
        int n = i >> 7, k = i & 127;
        int gn = n0 + n;
        sx[n][k] = (gn < N) ? __ldcs(&x[gn * 128 + k]) : 0.f;
    }
    __syncthreads();
    {
        int n1 = t >> 4, n2 = 16 + (t >> 4), c = t & 15;
        float a1 = b[c], a2 = a1;
#pragma unroll 16
        for (int k = 0; k < 128; k++) {
            float wv = sW[k * 16 + c];
            a1 += sx[n1][k] * wv;
            a2 += sx[n2][k] * wv;
        }
        sy[n1][c] = a1;
        sy[n2][c] = a2;
    }
    __syncthreads();
    if (t < 32) {
        int gn = n0 + t;
        if (gn < N) {
            float mu = 0.f;
#pragma unroll
            for (int c = 0; c < 16; c++) mu += sy[t][c];
            mu *= (1.f / 16.f);
            float var = 0.f;
#pragma unroll
            for (int c = 0; c < 16; c++) { float d = sy[t][c] - mu; var += d * d; }
            var *= (1.f / 16.f);
            float inv = rsqrtf(var + EPSV);
#pragma unroll
            for (int c = 0; c < 16; c++) {
                float v = fmaxf((sy[t][c] - mu) * inv * lnw[c] + lnb[c], 0.f);
                sy[t][c] = v;
                d_h[gn * 16 + c] = v;
                out[gn * 16 + c] = v;
            }
        }
    }
    __syncthreads();
    // transform phase: 32 nodes x 32 channels
    int c = t & 31, nb = t >> 5;
#pragma unroll
    for (int j = 0; j < 4; j++) {
        int nl = nb + j * 8;
        int gn = n0 + nl;
        if (gn < N) {
            float al = sbl[c], ar = sbr[c];
#pragma unroll
            for (int k = 0; k < 16; k++) {
                float hv = sy[nl][k];
                al += hv * sWl[k * 32 + c];
                ar += hv * sWr[k * 32 + c];
            }
            d_xl[gn * 32 + c] = al;
            d_xr[gn * 32 + c] = ar;
            d_g [gn * 32 + c] = 0.f;
        }
    }
    if (t < 64) {
        int gn = n0 + (t >> 1);
        if (gn < N) d_den[gn * 2 + (t & 1)] = 0.f;
    }
}

// ---------------- K_edge: per-edge pass (8 lanes / edge), chunked ----------------
__global__ void __launch_bounds__(256) k_edge(
    const float4* __restrict__ eattr,
    const float* __restrict__ We, const float* __restrict__ att,
    int e_begin, int e_end, int N, int zeroStats)
{
    __shared__ float4 sWe[32];  // We[4][32] as float4
    __shared__ float4 sAtt[8];  // att[2][16] as 8 float4
    int t = threadIdx.x;
    if (zeroStats && blockIdx.x == 0 && t >= 64 && t < 68) d_stats[t - 64] = 0.0;
    if (t < 32) sWe[t] = ((const float4*)We)[t];
    else if (t < 40) sAtt[t - 32] = ((const float4*)att)[t - 32];
    __syncthreads();

    int lane = t & 7;
    int head = lane >> 2;
    unsigned smask = 0xFu << ((t & 31) & ~3);  // 4-lane subgroup (one head of one edge)
    int e = e_begin + ((blockIdx.x * 256 + t) >> 3);
    if (e >= e_end) return;

    int s = min(max(__ldcs(&d_src[e]), 0), N - 1);
    int d = min(max(__ldcs(&d_dst[e]), 0), N - 1);
    const float4* xl4 = (const float4*)d_xl;
    const float4* xr4 = (const float4*)d_xr;
    float4 a  = __ldg(&xl4[s * 8 + lane]);
    float4 bb = __ldg(&xr4[d * 8 + lane]);
    float4 ea = __ldcs(&eattr[e]);
    float4 w0 = sWe[lane], w1 = sWe[8 + lane], w2 = sWe[16 + lane], w3 = sWe[24 + lane];

    float mx = a.x + bb.x + ea.x * w0.x + ea.y * w1.x + ea.z * w2.x + ea.w * w3.x;
    float my = a.y + bb.y + ea.x * w0.y + ea.y * w1.y + ea.z * w2.y + ea.w * w3.y;
    float mz = a.z + bb.z + ea.x * w0.z + ea.y * w1.z + ea.z * w2.z + ea.w * w3.z;
    float mw = a.w + bb.w + ea.x * w0.w + ea.y * w1.w + ea.z * w2.w + ea.w * w3.w;
    mx = leaky(mx); my = leaky(my); mz = leaky(mz); mw = leaky(mw);

    float4 at = sAtt[lane];
    float p = mx * at.x + my * at.y + mz * at.z + mw * at.w;
    p += __shfl_xor_sync(smask, p, 1);
    p += __shfl_xor_sync(smask, p, 2);
    float ex = __expf(p);   // shift-free softmax

    if ((lane & 3) == 0) atomicAdd(&d_den[d * 2 + head], ex);

    unsigned long long gp = (unsigned long long)__cvta_generic_to_global(&d_g[d * 32 + lane * 4]);
    asm volatile("red.global.add.v4.f32 [%0], {%1,%2,%3,%4};"
                 :: "l"(gp), "f"(ex * a.x), "f"(ex * a.y), "f"(ex * a.z), "f"(ex * a.w)
                 : "memory");
}

// ------- K_final: self-loop + normalize by den + gat_b; accumulate norm1 stats ---
__global__ void __launch_bounds__(256) k_final(
    const float* __restrict__ att, const float* __restrict__ gatb, int N)
{
    __shared__ float4 sAtt[8];
    int t = threadIdx.x;
    if (t < 8) sAtt[t] = ((const float4*)att)[t];
    __syncthreads();

    int lane = t & 7;
    int head = lane >> 2;
    unsigned smask = 0xFu << ((t & 31) & ~3);
    int n = (blockIdx.x * 256 + t) >> 3;

    float s_loc = 0.f, q_loc = 0.f;
    if (n < N) {
        const float4* xl4 = (const float4*)d_xl;
        const float4* xr4 = (const float4*)d_xr;
        float4 a  = xl4[n * 8 + lane];
        float4 bb = xr4[n * 8 + lane];
        float mx = leaky(a.x + bb.x);
        float my = leaky(a.y + bb.y);
        float mz = leaky(a.z + bb.z);
        float mw = leaky(a.w + bb.w);
        float4 at = sAtt[lane];
        float p = mx * at.x + my * at.y + mz * at.z + mw * at.w;
        p += __shfl_xor_sync(smask, p, 1);
        p += __shfl_xor_sync(smask, p, 2);
        float ex = __expf(p);
        float inv = 1.f / (d_den[n * 2 + head] + ex);
        float4 g  = ((const float4*)d_g)[n * 8 + lane];
        float4 gb = ((const float4*)gatb)[lane];
        float rx = (g.x + ex * a.x) * inv + gb.x;
        float ry = (g.y + ex * a.y) * inv + gb.y;
        float rz = (g.z + ex * a.z) * inv + gb.z;
        float rw = (g.w + ex * a.w) * inv + gb.w;
        ((float4*)d_g)[n * 8 + lane] = make_float4(rx, ry, rz, rw);
        s_loc = rx + ry + rz + rw;
        q_loc = rx * rx + ry * ry + rz * rz + rw * rw;
    }
    blockReduceAdd2(s_loc, q_loc, &d_stats[0], &d_stats[1]);
}

// ------- K_lin: graph_LN(g)+relu, u = t @ linW + linb; accumulate norm2 stats ----
__global__ void __launch_bounds__(256) k_lin(
    const float* __restrict__ n1w, const float* __restrict__ n1b,
    const float* __restrict__ linW, const float* __restrict__ linb, int N)
{
    __shared__ float st[16][33];
    __shared__ float sW[512];
    __shared__ float sb[16];
    int t = threadIdx.x;
    int n0 = blockIdx.x * 16;
    for (int i = t; i < 512; i += 256) sW[i] = linW[i];
    if (t < 16) sb[t] = linb[t];

    double mu_d  = d_stats[0] / (32.0 * N);
    double var_d = d_stats[1] / (32.0 * N) - mu_d * mu_d;
    float mu  = (float)mu_d;
    float inv = rsqrtf((float)var_d + EPSV);

#pragma unroll
    for (int r = 0; r < 2; r++) {
        int i = t + r * 256;
        int nl = i >> 5, k = i & 31;
        int gn = n0 + nl;
        float v = 0.f;
        if (gn < N) {
            v = (d_g[gn * 32 + k] - mu) * inv * n1w[k] + n1b[k];
            v = fmaxf(v, 0.f);
        }
        st[nl][k] = v;
    }
    __syncthreads();

    int nl = t >> 4, c = t & 15;
    int gn = n0 + nl;
    float s_loc = 0.f, q_loc = 0.f;
    if (gn < N) {
        float acc = sb[c];
#pragma unroll
        for (int k = 0; k < 32; k++) acc += st[nl][k] * sW[k * 16 + c];
        d_u[gn * 16 + c] = acc;
        s_loc = acc;
        q_loc = acc * acc;
    }
    blockReduceAdd2(s_loc, q_loc, &d_stats[2], &d_stats[3]);
}

// ------- K_resid_tf: graph_LN(u)+resid+relu -> h; out=max; next-layer transform ---
// 64 nodes per block of 256 threads.
__global__ void __launch_bounds__(256) k_resid_tf(
    const float* __restrict__ n2w, const float* __restrict__ n2b,
    const float* __restrict__ Wl, const float* __restrict__ bl,
    const float* __restrict__ Wr, const float* __restrict__ br,
    float* __restrict__ out, int N)
{
    __shared__ float sh[64][17];
    __shared__ float sWl[512], sWr[512], sbl[32], sbr[32];
    int t = threadIdx.x;
    int n0 = blockIdx.x * 64;
    for (int i = t; i < 512; i += 256) { sWl[i] = Wl[i]; sWr[i] = Wr[i]; }
    if (t < 32) { sbl[t] = bl[t]; sbr[t] = br[t]; }

    double mu_d  = d_stats[2] / (16.0 * N);
    double var_d = d_stats[3] / (16.0 * N) - mu_d * mu_d;
    float mu  = (float)mu_d;
    float inv = rsqrtf((float)var_d + EPSV);

#pragma unroll
    for (int r = 0; r < 4; r++) {
        int li = t + r * 256;
        int nl = li >> 4, c = li & 15;
        int gn = n0 + nl;
        float hn = 0.f;
        if (gn < N) {
            int i = gn * 16 + c;
            float v = (d_u[i] - mu) * inv * n2w[c] + n2b[c];
            hn = fmaxf(v + d_h[i], 0.f);
            d_h[i] = hn;
            out[i] = fmaxf(out[i], hn);
        }
        sh[nl][c] = hn;
    }
    __syncthreads();

    int c = t & 31, w = t >> 5;
#pragma unroll
    for (int j = 0; j < 8; j++) {
        int nl = w * 8 + j;
        int gn = n0 + nl;
        if (gn >= N) break;   // warp-uniform
        float al = sbl[c], ar = sbr[c];
#pragma unroll
        for (int k = 0; k < 16; k++) {
            float hv = sh[nl][k];
            al += hv * sWl[k * 32 + c];
            ar += hv * sWr[k * 32 + c];
        }
        d_xl[gn * 32 + c] = al;
        d_xr[gn * 32 + c] = ar;
        d_g [gn * 32 + c] = 0.f;
    }
    if (t < 128) {
        int gn = n0 + (t >> 1);
        if (gn < N) d_den[gn * 2 + (t & 1)] = 0.f;
    }
}

// ------- K_resid (last layer): graph_LN(u)+resid+relu; out = max(out, h) ---------
__global__ void __launch_bounds__(256) k_resid(
    const float* __restrict__ n2w, const float* __restrict__ n2b,
    float* __restrict__ out, int N)
{
    int i = blockIdx.x * 256 + threadIdx.x;
    if (i >= N * 16) return;
    int c = i & 15;
    double mu_d  = d_stats[2] / (16.0 * N);
    double var_d = d_stats[3] / (16.0 * N) - mu_d * mu_d;
    float mu  = (float)mu_d;
    float inv = rsqrtf((float)var_d + EPSV);
    float v  = (d_u[i] - mu) * inv * n2w[c] + n2b[c];
    float hn = fmaxf(v + d_h[i], 0.f);
    out[i] = fmaxf(out[i], hn);
}

// ---------------- launch ----------------
extern "C" void kernel_launch(void* const* d_in, const int* in_sizes, int n_in,
                              void* d_out, int out_size)
{
    const float* x     = (const float*)d_in[0];
    const int*   ei32  = (const int*)d_in[1];
    const float* eattr = (const float*)d_in[2];
    const float* embW  = (const float*)d_in[3];
    const float* embB  = (const float*)d_in[4];
    const float* ln0w  = (const float*)d_in[5];
    const float* ln0b  = (const float*)d_in[6];
    const float* Wl    = (const float*)d_in[7];
    const float* bl    = (const float*)d_in[8];
    const float* Wr    = (const float*)d_in[9];
    const float* br    = (const float*)d_in[10];
    const float* We    = (const float*)d_in[11];
    const float* att   = (const float*)d_in[12];
    const float* gatb  = (const float*)d_in[13];
    const float* n1w   = (const float*)d_in[14];
    const float* n1b   = (const float*)d_in[15];
    const float* linW  = (const float*)d_in[16];
    const float* linb  = (const float*)d_in[17];
    const float* n2w   = (const float*)d_in[18];
    const float* n2b   = (const float*)d_in[19];
    float* out = (float*)d_out;

    int N = in_sizes[0] / 128;
    int E = in_sizes[1] / 2;
    int Ec = (E + EDGE_CHUNKS - 1) / EDGE_CHUNKS;

    k_detect<<<1, 256>>>(ei32, in_sizes[1]);
    k_conv  <<<(E + 255) / 256, 256>>>(ei32, E);
    k_embed_tf<<<(N + 31) / 32, 256>>>(x, embW, embB, ln0w, ln0b,
                                       Wl, bl, Wr, br, out, N);

    for (int l = 0; l < 2; l++) {
        for (int cchunk = 0; cchunk < EDGE_CHUNKS; cchunk++) {
            int e0 = cchunk * Ec;
            int e1 = min(e0 + Ec, E);
            if (e0 >= e1) continue;
            int nthr = (e1 - e0) * 8;
            k_edge<<<(nthr + 255) / 256, 256>>>((const float4*)eattr,
                                                We + l * 128, att + l * 32,
                                                e0, e1, N, cchunk == 0);
        }
        k_final<<<(N * 8 + 255) / 256, 256>>>(att + l * 32, gatb + l * 32, N);
        k_lin  <<<(N + 15) / 16, 256>>>(n1w + l * 32, n1b + l * 32,
                                        linW + l * 512, linb + l * 16, N);
        if (l == 0) {
            k_resid_tf<<<(N + 63) / 64, 256>>>(n2w + l * 16, n2b + l * 16,
                                               Wl + 512, bl + 32, Wr + 512, br + 32,
                                               out, N);
        } else {
            k_resid<<<(N * 16 + 255) / 256, 256>>>(n2w + l * 16, n2b + l * 16, out, N);
        }
    }
}

// round 4
// speedup vs baseline: 1.0688x; 1.0498x over previous
#include <cuda_runtime.h>

#define EPSV 1e-5f
#define NMAX 100000
#define EMAX 1600000
#define SCAN_BLK 512

// ---------------- scratch (device globals; no allocation allowed) -------------
__device__ alignas(16) float  d_h  [NMAX * 16];
__device__ alignas(16) float  d_xl [NMAX * 32];
__device__ alignas(16) float  d_xr [NMAX * 32];
__device__ alignas(16) float  d_g  [NMAX * 32];
__device__ alignas(16) float  d_u  [NMAX * 16];
__device__ int    d_src [EMAX];
__device__ int    d_dst [EMAX];
__device__ int    d_srcp[EMAX];          // src permuted into dst-grouped order
__device__ alignas(16) float4 d_eap[EMAX]; // edge_attr permuted
__device__ int    d_cnt [NMAX];
__device__ int    d_incl[NMAX];
__device__ int    d_off [NMAX];
__device__ int    d_cur [NMAX];
__device__ int    d_bsum[256];
__device__ double d_stats[4];  // [0],[1]: sum/sumsq of g; [2],[3]: of u
__device__ int    d_is64;

// ---------------- helpers ----------------
__device__ __forceinline__ float leaky(float v) { return v > 0.f ? v : 0.2f * v; }

__device__ __forceinline__ void blockReduceAdd2(float s, float q, double* o0, double* o1) {
    __shared__ float rs[8], rq[8];
#pragma unroll
    for (int o = 16; o; o >>= 1) {
        s += __shfl_xor_sync(0xffffffffu, s, o);
        q += __shfl_xor_sync(0xffffffffu, q, o);
    }
    int w = threadIdx.x >> 5, l = threadIdx.x & 31;
    if (l == 0) { rs[w] = s; rq[w] = q; }
    __syncthreads();
    if (w == 0) {
        s = (l < 8) ? rs[l] : 0.f;
        q = (l < 8) ? rq[l] : 0.f;
#pragma unroll
        for (int o = 4; o; o >>= 1) {
            s += __shfl_xor_sync(0xffffffffu, s, o);
            q += __shfl_xor_sync(0xffffffffu, q, o);
        }
        if (l == 0) { atomicAdd(o0, (double)s); atomicAdd(o1, (double)q); }
    }
}

// ------- K_detect: int64-vs-int32 sniff + zero cnt + zero stats (1 block) -------
__global__ void k_detect(const int* __restrict__ ei32, int E2, int N) {
    __shared__ int allzero;
    if (threadIdx.x == 0) allzero = 1;
    __syncthreads();
    long long idx = 2LL * threadIdx.x + 1;
    if (idx < E2 && ei32[idx] != 0) allzero = 0;   // benign race
    __syncthreads();
    if (threadIdx.x == 0) d_is64 = allzero;
    if (threadIdx.x < 4) d_stats[threadIdx.x] = 0.0;
    for (int i = threadIdx.x; i < N; i += 256) d_cnt[i] = 0;
}

// ------- K_conv: decode edge_index -> clamped int32 src/dst + dst histogram -------
__global__ void __launch_bounds__(256) k_conv(const int* __restrict__ ei32, int E, int N) {
    int i = blockIdx.x * 256 + threadIdx.x;
    if (i >= E) return;
    int s, d;
    if (d_is64) {
        const long long* e64 = (const long long*)ei32;
        s = (int)__ldcs(&e64[i]);
        d = (int)__ldcs(&e64[E + i]);
    } else {
        s = __ldcs(&ei32[i]);
        d = __ldcs(&ei32[E + i]);
    }
    s = min(max(s, 0), N - 1);
    d = min(max(d, 0), N - 1);
    d_src[i] = s;
    d_dst[i] = d;
    atomicAdd(&d_cnt[d], 1);
}

// ------- K_scan1: per-512-block inclusive scan of cnt -------
__global__ void __launch_bounds__(SCAN_BLK) k_scan1(int N) {
    __shared__ int s[SCAN_BLK];
    int i = blockIdx.x * SCAN_BLK + threadIdx.x;
    int v = (i < N) ? d_cnt[i] : 0;
    s[threadIdx.x] = v;
    __syncthreads();
#pragma unroll
    for (int o = 1; o < SCAN_BLK; o <<= 1) {
        int u = (threadIdx.x >= o) ? s[threadIdx.x - o] : 0;
        __syncthreads();
        s[threadIdx.x] += u;
        __syncthreads();
    }
    if (i < N) d_incl[i] = s[threadIdx.x];
    if (threadIdx.x == SCAN_BLK - 1) d_bsum[blockIdx.x] = s[threadIdx.x];
}

// ------- K_scan2: scan block sums (1 block) + write offsets & cursors -------
__global__ void __launch_bounds__(1024) k_scan2(int N, int nb) {
    __shared__ int sb[256];
    int t = threadIdx.x;
    if (t < 256) sb[t] = (t < nb) ? d_bsum[t] : 0;
    __syncthreads();
#pragma unroll
    for (int o = 1; o < 256; o <<= 1) {
        int u = 0;
        if (t < 256 && t >= o) u = sb[t - o];
        __syncthreads();
        if (t < 256) sb[t] += u;
        __syncthreads();
    }
    for (int i = t; i < N; i += 1024) {
        int blk = i >> 9;
        int base = blk ? sb[blk - 1] : 0;
        int start = base + d_incl[i] - d_cnt[i];
        d_off[i] = start;
        d_cur[i] = start;
    }
}

// ------- K_scatter: permute (src, eattr) into dst-grouped order -------
__global__ void __launch_bounds__(256) k_scatter(const float4* __restrict__ eattr, int E) {
    int i = blockIdx.x * 256 + threadIdx.x;
    if (i >= E) return;
    int d = d_dst[i];
    int pos = atomicAdd(&d_cur[d], 1);
    d_srcp[pos] = d_src[i];
    d_eap[pos]  = __ldcs(&eattr[i]);
}

// ------- K_embed_tf: h = relu(node_LN(x@W+b)); out=h; xl/xr for layer 0 -------
__global__ void __launch_bounds__(256) k_embed_tf(
    const float* __restrict__ x, const float* __restrict__ W,
    const float* __restrict__ b, const float* __restrict__ lnw,
    const float* __restrict__ lnb,
    const float* __restrict__ Wl, const float* __restrict__ bl,
    const float* __restrict__ Wr, const float* __restrict__ br,
    float* __restrict__ out, int N)
{
    __shared__ float sx[32][132];
    __shared__ float sW[2048];
    __shared__ float sy[32][17];
    __shared__ float sWl[512], sWr[512], sbl[32], sbr[32];
    int t = threadIdx.x;
    int n0 = blockIdx.x * 32;
    for (int i = t; i < 2048; i += 256) sW[i] = W[i];
    for (int i = t; i < 512; i += 256) { sWl[i] = Wl[i]; sWr[i] = Wr[i]; }
    if (t < 32) { sbl[t] = bl[t]; sbr[t] = br[t]; }
    // x loads as float4 (rows padded to 132 floats so every row stays 16B aligned)
    for (int i = t; i < 1024; i += 256) {
        int n = i >> 5, k4 = i & 31;
        int gn = n0 + n;
        float4 v = (gn < N) ? __ldcs(&((const float4*)x)[gn * 32 + k4])
                            : make_float4(0.f, 0.f, 0.f, 0.f);
        *(float4*)&sx[n][k4 * 4] = v;
    }
    __syncthreads();
    {
        int n1 = t >> 4, n2 = 16 + (t >> 4), c = t & 15;
        float a1 = b[c], a2 = a1;
#pragma unroll 16
        for (int k = 0; k < 128; k++) {
            float wv = sW[k * 16 + c];
            a1 += sx[n1][k] * wv;
            a2 += sx[n2][k] * wv;
        }
        sy[n1][c] = a1;
        sy[n2][c] = a2;
    }
    __syncthreads();
    if (t < 32) {
        int gn = n0 + t;
        if (gn < N) {
            float mu = 0.f;
#pragma unroll
            for (int c = 0; c < 16; c++) mu += sy[t][c];
            mu *= (1.f / 16.f);
            float var = 0.f;
#pragma unroll
            for (int c = 0; c < 16; c++) { float d = sy[t][c] - mu; var += d * d; }
            var *= (1.f / 16.f);
            float inv = rsqrtf(var + EPSV);
#pragma unroll
            for (int c = 0; c < 16; c++) {
                float v = fmaxf((sy[t][c] - mu) * inv * lnw[c] + lnb[c], 0.f);
                sy[t][c] = v;
                d_h[gn * 16 + c] = v;
                out[gn * 16 + c] = v;
            }
        }
    }
    __syncthreads();
    int c = t & 31, nb = t >> 5;
#pragma unroll
    for (int j = 0; j < 4; j++) {
        int nl = nb + j * 8;
        int gn = n0 + nl;
        if (gn < N) {
            float al = sbl[c], ar = sbr[c];
#pragma unroll
            for (int k = 0; k < 16; k++) {
                float hv = sy[nl][k];
                al += hv * sWl[k * 32 + c];
                ar += hv * sWr[k * 32 + c];
            }
            d_xl[gn * 32 + c] = al;
            d_xr[gn * 32 + c] = ar;
        }
    }
}

// ------- K_edge_csr: per-dst-node aggregation (8 lanes/node, CSR, no atomics) ----
// Fuses: message+logit+exp, unnormalized accumulation, self-loop, normalization,
// gat_b, and norm1 stats. Writes g once per node.
__global__ void __launch_bounds__(256) k_edge_csr(
    const float* __restrict__ We, const float* __restrict__ att,
    const float* __restrict__ gatb, int N, int zero23)
{
    __shared__ float4 sWe[32];  // We[4][32] as float4
    __shared__ float4 sAtt[8];  // att[2][16] as 8 float4
    __shared__ float4 sGb[8];
    int t = threadIdx.x;
    if (zero23 && blockIdx.x == 0 && t >= 64 && t < 66) d_stats[2 + (t - 64)] = 0.0;
    if (t < 32) sWe[t] = ((const float4*)We)[t];
    else if (t < 40) sAtt[t - 32] = ((const float4*)att)[t - 32];
    else if (t < 48) sGb[t - 40] = ((const float4*)gatb)[t - 40];
    __syncthreads();

    int lane = t & 7;
    unsigned smask = 0xFu << ((t & 31) & ~3);  // 4-lane subgroup (one head)
    int n = (blockIdx.x * 256 + t) >> 3;

    float s_loc = 0.f, q_loc = 0.f;
    if (n < N) {
        const float4* xl4 = (const float4*)d_xl;
        float4 xr = ((const float4*)d_xr)[n * 8 + lane];
        float4 w0 = sWe[lane], w1 = sWe[8 + lane], w2 = sWe[16 + lane], w3 = sWe[24 + lane];
        float4 at = sAtt[lane];

        // self-loop (ew = 0)
        float4 a0 = xl4[n * 8 + lane];
        float p = leaky(a0.x + xr.x) * at.x + leaky(a0.y + xr.y) * at.y
                + leaky(a0.z + xr.z) * at.z + leaky(a0.w + xr.w) * at.w;
        p += __shfl_xor_sync(smask, p, 1);
        p += __shfl_xor_sync(smask, p, 2);
        float ex = __expf(p);   // shift-free softmax
        float den = ex;
        float4 acc = make_float4(ex * a0.x, ex * a0.y, ex * a0.z, ex * a0.w);

        int start = d_off[n], deg = d_cnt[n];
        int sj = 0; float4 eaj = make_float4(0.f, 0.f, 0.f, 0.f);
        if (deg > 0) { sj = __ldcs(&d_srcp[start]); eaj = __ldcs(&d_eap[start]); }
        for (int j = 0; j < deg; j++) {
            int s = sj; float4 ea = eaj;
            if (j + 1 < deg) {
                sj  = __ldcs(&d_srcp[start + j + 1]);
                eaj = __ldcs(&d_eap[start + j + 1]);
            }
            float4 a = __ldg(&xl4[s * 8 + lane]);
            float mx = a.x + xr.x + ea.x * w0.x + ea.y * w1.x + ea.z * w2.x + ea.w * w3.x;
            float my = a.y + xr.y + ea.x * w0.y + ea.y * w1.y + ea.z * w2.y + ea.w * w3.y;
            float mz = a.z + xr.z + ea.x * w0.z + ea.y * w1.z + ea.z * w2.z + ea.w * w3.z;
            float mw = a.w + xr.w + ea.x * w0.w + ea.y * w1.w + ea.z * w2.w + ea.w * w3.w;
            float pe = leaky(mx) * at.x + leaky(my) * at.y + leaky(mz) * at.z + leaky(mw) * at.w;
            pe += __shfl_xor_sync(smask, pe, 1);
            pe += __shfl_xor_sync(smask, pe, 2);
            float exe = __expf(pe);
            den += exe;
            acc.x += exe * a.x; acc.y += exe * a.y;
            acc.z += exe * a.z; acc.w += exe * a.w;
        }
        float inv = 1.f / den;   // den identical across the 4 lanes of a head
        float4 gb = sGb[lane];
        float rx = acc.x * inv + gb.x;
        float ry = acc.y * inv + gb.y;
        float rz = acc.z * inv + gb.z;
        float rw = acc.w * inv + gb.w;
        ((float4*)d_g)[n * 8 + lane] = make_float4(rx, ry, rz, rw);
        s_loc = rx + ry + rz + rw;
        q_loc = rx * rx + ry * ry + rz * rz + rw * rw;
    }
    blockReduceAdd2(s_loc, q_loc, &d_stats[0], &d_stats[1]);
}

// ------- K_lin: graph_LN(g)+relu, u = t @ linW + linb; accumulate norm2 stats ----
__global__ void __launch_bounds__(256) k_lin(
    const float* __restrict__ n1w, const float* __restrict__ n1b,
    const float* __restrict__ linW, const float* __restrict__ linb, int N)
{
    __shared__ float st[16][33];
    __shared__ float sW[512];
    __shared__ float sb[16];
    int t = threadIdx.x;
    int n0 = blockIdx.x * 16;
    for (int i = t; i < 512; i += 256) sW[i] = linW[i];
    if (t < 16) sb[t] = linb[t];

    double mu_d  = d_stats[0] / (32.0 * N);
    double var_d = d_stats[1] / (32.0 * N) - mu_d * mu_d;
    float mu  = (float)mu_d;
    float inv = rsqrtf((float)var_d + EPSV);

#pragma unroll
    for (int r = 0; r < 2; r++) {
        int i = t + r * 256;
        int nl = i >> 5, k = i & 31;
        int gn = n0 + nl;
        float v = 0.f;
        if (gn < N) {
            v = (d_g[gn * 32 + k] - mu) * inv * n1w[k] + n1b[k];
            v = fmaxf(v, 0.f);
        }
        st[nl][k] = v;
    }
    __syncthreads();

    int nl = t >> 4, c = t & 15;
    int gn = n0 + nl;
    float s_loc = 0.f, q_loc = 0.f;
    if (gn < N) {
        float acc = sb[c];
#pragma unroll
        for (int k = 0; k < 32; k++) acc += st[nl][k] * sW[k * 16 + c];
        d_u[gn * 16 + c] = acc;
        s_loc = acc;
        q_loc = acc * acc;
    }
    blockReduceAdd2(s_loc, q_loc, &d_stats[2], &d_stats[3]);
}

// ------- K_resid_tf: graph_LN(u)+resid+relu -> h; out=max; next-layer xl/xr -------
__global__ void __launch_bounds__(256) k_resid_tf(
    const float* __restrict__ n2w, const float* __restrict__ n2b,
    const float* __restrict__ Wl, const float* __restrict__ bl,
    const float* __restrict__ Wr, const float* __restrict__ br,
    float* __restrict__ out, int N)
{
    __shared__ float sh[64][17];
    __shared__ float sWl[512], sWr[512], sbl[32], sbr[32];
    int t = threadIdx.x;
    int n0 = blockIdx.x * 64;
    if (blockIdx.x == 0 && t >= 128 && t < 130) d_stats[t - 128] = 0.0; // zero norm1 stats for next layer
    for (int i = t; i < 512; i += 256) { sWl[i] = Wl[i]; sWr[i] = Wr[i]; }
    if (t < 32) { sbl[t] = bl[t]; sbr[t] = br[t]; }

    double mu_d  = d_stats[2] / (16.0 * N);
    double var_d = d_stats[3] / (16.0 * N) - mu_d * mu_d;
    float mu  = (float)mu_d;
    float inv = rsqrtf((float)var_d + EPSV);

#pragma unroll
    for (int r = 0; r < 4; r++) {
        int li = t + r * 256;
        int nl = li >> 4, c = li & 15;
        int gn = n0 + nl;
        float hn = 0.f;
        if (gn < N) {
            int i = gn * 16 + c;
            float v = (d_u[i] - mu) * inv * n2w[c] + n2b[c];
            hn = fmaxf(v + d_h[i], 0.f);
            d_h[i] = hn;
            out[i] = fmaxf(out[i], hn);
        }
        sh[nl][c] = hn;
    }
    __syncthreads();

    int c = t & 31, w = t >> 5;
#pragma unroll
    for (int j = 0; j < 8; j++) {
        int nl = w * 8 + j;
        int gn = n0 + nl;
        if (gn >= N) break;   // warp-uniform
        float al = sbl[c], ar = sbr[c];
#pragma unroll
        for (int k = 0; k < 16; k++) {
            float hv = sh[nl][k];
            al += hv * sWl[k * 32 + c];
            ar += hv * sWr[k * 32 + c];
        }
        d_xl[gn * 32 + c] = al;
        d_xr[gn * 32 + c] = ar;
    }
}

// ------- K_resid (last layer): graph_LN(u)+resid+relu; out = max(out, h) ---------
__global__ void __launch_bounds__(256) k_resid(
    const float* __restrict__ n2w, const float* __restrict__ n2b,
    float* __restrict__ out, int N)
{
    int i = blockIdx.x * 256 + threadIdx.x;
    if (i >= N * 16) return;
    int c = i & 15;
    double mu_d  = d_stats[2] / (16.0 * N);
    double var_d = d_stats[3] / (16.0 * N) - mu_d * mu_d;
    float mu  = (float)mu_d;
    float inv = rsqrtf((float)var_d + EPSV);
    float v  = (d_u[i] - mu) * inv * n2w[c] + n2b[c];
    float hn = fmaxf(v + d_h[i], 0.f);
    out[i] = fmaxf(out[i], hn);
}

// ---------------- launch ----------------
extern "C" void kernel_launch(void* const* d_in, const int* in_sizes, int n_in,
                              void* d_out, int out_size)
{
    const float* x     = (const float*)d_in[0];
    const int*   ei32  = (const int*)d_in[1];
    const float* eattr = (const float*)d_in[2];
    const float* embW  = (const float*)d_in[3];
    const float* embB  = (const float*)d_in[4];
    const float* ln0w  = (const float*)d_in[5];
    const float* ln0b  = (const float*)d_in[6];
    const float* Wl    = (const float*)d_in[7];
    const float* bl    = (const float*)d_in[8];
    const float* Wr    = (const float*)d_in[9];
    const float* br    = (const float*)d_in[10];
    const float* We    = (const float*)d_in[11];
    const float* att   = (const float*)d_in[12];
    const float* gatb  = (const float*)d_in[13];
    const float* n1w   = (const float*)d_in[14];
    const float* n1b   = (const float*)d_in[15];
    const float* linW  = (const float*)d_in[16];
    const float* linb  = (const float*)d_in[17];
    const float* n2w   = (const float*)d_in[18];
    const float* n2b   = (const float*)d_in[19];
    float* out = (float*)d_out;

    int N = in_sizes[0] / 128;
    int E = in_sizes[2] / 4;          // edge_attr is (E, 4) — unambiguous
    int nb1 = (N + SCAN_BLK - 1) / SCAN_BLK;

    // preprocessing (once): decode + counting-sort edges by dst
    k_detect <<<1, 256>>>(ei32, 2 * E, N);
    k_conv   <<<(E + 255) / 256, 256>>>(ei32, E, N);
    k_scan1  <<<nb1, SCAN_BLK>>>(N);
    k_scan2  <<<1, 1024>>>(N, nb1);
    k_scatter<<<(E + 255) / 256, 256>>>((const float4*)eattr, E);

    k_embed_tf<<<(N + 31) / 32, 256>>>(x, embW, embB, ln0w, ln0b,
                                       Wl, bl, Wr, br, out, N);  // launch #6 -> ncu

    for (int l = 0; l < 2; l++) {
        k_edge_csr<<<(N * 8 + 255) / 256, 256>>>(We + l * 128, att + l * 32,
                                                 gatb + l * 32, N, l == 1);
        k_lin<<<(N + 15) / 16, 256>>>(n1w + l * 32, n1b + l * 32,
                                      linW + l * 512, linb + l * 16, N);
        if (l == 0) {
            k_resid_tf<<<(N + 63) / 64, 256>>>(n2w, n2b,
                                               Wl + 512, bl + 32, Wr + 512, br + 32,
                                               out, N);
        } else {
            k_resid<<<(N * 16 + 255) / 256, 256>>>(n2w + 16, n2b + 16, out, N);
        }
    }
}

// round 5
// speedup vs baseline: 1.1247x; 1.0523x over previous
#include <cuda_runtime.h>

#define EPSV 1e-5f
#define NMAX 100000
#define EMAX 1600000
#define PB   512

// ---------------- scratch (device globals; no allocation allowed) -------------
__device__ alignas(16) float  d_h  [NMAX * 16];
__device__ alignas(16) float  d_xl [NMAX * 32];
__device__ alignas(16) float  d_xr [NMAX * 32];
__device__ alignas(16) float  d_g  [NMAX * 32];
__device__ alignas(16) float  d_u  [NMAX * 16];
__device__ int    d_src [EMAX];
__device__ int    d_dst [EMAX];
__device__ int    d_srcp[EMAX];             // src permuted into dst-grouped order
__device__ alignas(16) float4 d_eap[EMAX];  // edge_attr permuted
__device__ int    d_cnt [NMAX];
__device__ int    d_off [NMAX];
__device__ int    d_cur [NMAX];
__device__ int    d_bsum[256];
__device__ unsigned long long d_barc[4];    // monotonic grid-barrier tickets
__device__ double d_stats[4];  // [0],[1]: sum/sumsq of g; [2],[3]: of u

// ---------------- helpers ----------------
__device__ __forceinline__ float leaky(float v) { return v > 0.f ? v : 0.2f * v; }

__device__ __forceinline__ void gridbar(int idx, int NB) {
    __syncthreads();
    if (threadIdx.x == 0) {
        __threadfence();
        unsigned long long tk = atomicAdd(&d_barc[idx], 1ULL);
        unsigned long long target = (tk / NB + 1ULL) * (unsigned long long)NB;
        while (atomicAdd(&d_barc[idx], 0ULL) < target) { __nanosleep(64); }
    }
    __syncthreads();
}

__device__ __forceinline__ void blockReduceAdd2(float s, float q, double* o0, double* o1) {
    __shared__ float rs[8], rq[8];
#pragma unroll
    for (int o = 16; o; o >>= 1) {
        s += __shfl_xor_sync(0xffffffffu, s, o);
        q += __shfl_xor_sync(0xffffffffu, q, o);
    }
    int w = threadIdx.x >> 5, l = threadIdx.x & 31;
    if (l == 0) { rs[w] = s; rq[w] = q; }
    __syncthreads();
    if (w == 0) {
        s = (l < 8) ? rs[l] : 0.f;
        q = (l < 8) ? rq[l] : 0.f;
#pragma unroll
        for (int o = 4; o; o >>= 1) {
            s += __shfl_xor_sync(0xffffffffu, s, o);
            q += __shfl_xor_sync(0xffffffffu, q, o);
        }
        if (l == 0) { atomicAdd(o0, (double)s); atomicAdd(o1, (double)q); }
    }
}

// ------- K_conv: decode edge_index (int64-or-int32 sniffed per-thread) -------
__global__ void __launch_bounds__(256) k_conv(const int* __restrict__ ei32, int E, int N) {
    // int64 little-endian with values < 2^31 => odd words all zero.
    // 8 sampled odd words all zero under int32 has prob ~ (1/N)^8 ~ 0.
    bool is64 = true;
#pragma unroll
    for (int k = 0; k < 8; k++)
        if (__ldg(&ei32[2 * k + 1]) != 0) is64 = false;
    int i = blockIdx.x * 256 + threadIdx.x;
    if (i >= E) return;
    int s, d;
    if (is64) {
        const long long* e64 = (const long long*)ei32;
        s = (int)__ldcs(&e64[i]);
        d = (int)__ldcs(&e64[E + i]);
    } else {
        s = __ldcs(&ei32[i]);
        d = __ldcs(&ei32[E + i]);
    }
    s = min(max(s, 0), N - 1);
    d = min(max(d, 0), N - 1);
    d_src[i] = s;
    d_dst[i] = d;
}

// ------- K_prep: zero-hist -> histogram -> scan -> offsets -> scatter (1 launch) --
// NB blocks of PB threads; all co-resident (NB=196 <= 4/SM * 148 SMs).
__global__ void __launch_bounds__(PB) k_prep(const float4* __restrict__ eattr,
                                             int E, int N, int NB)
{
    __shared__ int ssc[PB];
    __shared__ int sbs[256];
    int t = threadIdx.x, b = blockIdx.x;
    int i = b * PB + t;
    int stride = NB * PB;

    // P0: zero counters + stats
    if (i < N) d_cnt[i] = 0;
    if (b == 0 && t < 4) d_stats[t] = 0.0;
    gridbar(0, NB);

    // P1: histogram of dst
    for (int e = b * PB + t; e < E; e += stride)
        atomicAdd(&d_cnt[d_dst[e]], 1);
    gridbar(1, NB);

    // P2: per-block inclusive scan of this block's 512-slice
    int v = (i < N) ? __ldcg(&d_cnt[i]) : 0;
    ssc[t] = v;
    __syncthreads();
#pragma unroll
    for (int o = 1; o < PB; o <<= 1) {
        int u = (t >= o) ? ssc[t - o] : 0;
        __syncthreads();
        ssc[t] += u;
        __syncthreads();
    }
    int incl = ssc[t];
    if (t == PB - 1) d_bsum[b] = incl;
    gridbar(2, NB);

    // P3: every block redundantly scans the NB block sums, writes its offsets
    if (t < 256) sbs[t] = (t < NB) ? __ldcg(&d_bsum[t]) : 0;
    __syncthreads();
#pragma unroll
    for (int o = 1; o < 256; o <<= 1) {
        int u = 0;
        if (t < 256 && t >= o) u = sbs[t - o];
        __syncthreads();
        if (t < 256) sbs[t] += u;
        __syncthreads();
    }
    int base = (b > 0) ? sbs[b - 1] : 0;
    if (i < N) {
        int off = base + incl - v;
        d_off[i] = off;
        d_cur[i] = off;
    }
    gridbar(3, NB);

    // P4: scatter (src, eattr) into dst-grouped order
    for (int e = b * PB + t; e < E; e += stride) {
        int d = d_dst[e];
        int pos = atomicAdd(&d_cur[d], 1);
        d_srcp[pos] = d_src[e];
        d_eap[pos]  = __ldcs(&eattr[e]);
    }
}

// ------- K_embed_tf: h = relu(node_LN(x@W+b)); out=h; xl/xr for layer 0 -------
__global__ void __launch_bounds__(256) k_embed_tf(
    const float* __restrict__ x, const float* __restrict__ W,
    const float* __restrict__ b, const float* __restrict__ lnw,
    const float* __restrict__ lnb,
    const float* __restrict__ Wl, const float* __restrict__ bl,
    const float* __restrict__ Wr, const float* __restrict__ br,
    float* __restrict__ out, int N)
{
    __shared__ float sx[32][132];
    __shared__ float sW[2048];
    __shared__ float sy[32][17];
    __shared__ float sWl[512], sWr[512], sbl[32], sbr[32];
    int t = threadIdx.x;
    int n0 = blockIdx.x * 32;
    for (int i = t; i < 2048; i += 256) sW[i] = W[i];
    for (int i = t; i < 512; i += 256) { sWl[i] = Wl[i]; sWr[i] = Wr[i]; }
    if (t < 32) { sbl[t] = bl[t]; sbr[t] = br[t]; }
    for (int i = t; i < 1024; i += 256) {
        int n = i >> 5, k4 = i & 31;
        int gn = n0 + n;
        float4 v = (gn < N) ? __ldcs(&((const float4*)x)[gn * 32 + k4])
                            : make_float4(0.f, 0.f, 0.f, 0.f);
        *(float4*)&sx[n][k4 * 4] = v;
    }
    __syncthreads();
    {
        int n1 = t >> 4, n2 = 16 + (t >> 4), c = t & 15;
        float a1 = b[c], a2 = a1;
#pragma unroll 16
        for (int k = 0; k < 128; k++) {
            float wv = sW[k * 16 + c];
            a1 += sx[n1][k] * wv;
            a2 += sx[n2][k] * wv;
        }
        sy[n1][c] = a1;
        sy[n2][c] = a2;
    }
    __syncthreads();
    if (t < 32) {
        int gn = n0 + t;
        if (gn < N) {
            float mu = 0.f;
#pragma unroll
            for (int c = 0; c < 16; c++) mu += sy[t][c];
            mu *= (1.f / 16.f);
            float var = 0.f;
#pragma unroll
            for (int c = 0; c < 16; c++) { float d = sy[t][c] - mu; var += d * d; }
            var *= (1.f / 16.f);
            float inv = rsqrtf(var + EPSV);
#pragma unroll
            for (int c = 0; c < 16; c++) {
                float v = fmaxf((sy[t][c] - mu) * inv * lnw[c] + lnb[c], 0.f);
                sy[t][c] = v;
                d_h[gn * 16 + c] = v;
                out[gn * 16 + c] = v;
            }
        }
    }
    __syncthreads();
    int c = t & 31, nb = t >> 5;
#pragma unroll
    for (int j = 0; j < 4; j++) {
        int nl = nb + j * 8;
        int gn = n0 + nl;
        if (gn < N) {
            float al = sbl[c], ar = sbr[c];
#pragma unroll
            for (int k = 0; k < 16; k++) {
                float hv = sy[nl][k];
                al += hv * sWl[k * 32 + c];
                ar += hv * sWr[k * 32 + c];
            }
            d_xl[gn * 32 + c] = al;
            d_xr[gn * 32 + c] = ar;
        }
    }
}

// ------- K_edge_csr: per-dst aggregation, software-pipelined (8 lanes/node) ------
// depth-4 index prefetch, depth-2 gather prefetch; no atomics, no scatter.
__global__ void __launch_bounds__(256) k_edge_csr(
    const float* __restrict__ We, const float* __restrict__ att,
    const float* __restrict__ gatb, int N, int zero23)
{
    __shared__ float4 sWe[32];
    __shared__ float4 sAtt[8];
    __shared__ float4 sGb[8];
    int t = threadIdx.x;
    if (zero23 && blockIdx.x == 0 && t >= 64 && t < 66) d_stats[2 + (t - 64)] = 0.0;
    if (t < 32) sWe[t] = ((const float4*)We)[t];
    else if (t < 40) sAtt[t - 32] = ((const float4*)att)[t - 32];
    else if (t < 48) sGb[t - 40] = ((const float4*)gatb)[t - 40];
    __syncthreads();

    int lane = t & 7;
    unsigned smask = 0xFu << ((t & 31) & ~3);
    int n = (blockIdx.x * 256 + t) >> 3;

    float s_loc = 0.f, q_loc = 0.f;
    if (n < N) {
        const float4* xl4 = (const float4*)d_xl;
        float4 xr = ((const float4*)d_xr)[n * 8 + lane];
        float4 w0 = sWe[lane], w1 = sWe[8 + lane], w2 = sWe[16 + lane], w3 = sWe[24 + lane];
        float4 at = sAtt[lane];

        // self-loop (ew = 0)
        float4 a0 = xl4[n * 8 + lane];
        float p = leaky(a0.x + xr.x) * at.x + leaky(a0.y + xr.y) * at.y
                + leaky(a0.z + xr.z) * at.z + leaky(a0.w + xr.w) * at.w;
        p += __shfl_xor_sync(smask, p, 1);
        p += __shfl_xor_sync(smask, p, 2);
        float ex = __expf(p);
        float den = ex;
        float4 acc = make_float4(ex * a0.x, ex * a0.y, ex * a0.z, ex * a0.w);

        int start = __ldg(&d_off[n]), deg = __ldg(&d_cnt[n]);
        const int*    sp = d_srcp + start;
        const float4* ep = d_eap + start;

        // pipeline state: A = edge j (ready), B = edge j+1 (gather in flight),
        // C = indices for j+2, D = indices for j+3
        float4 eaA, eaB, eaC, eaD, aA, aB;
        int sC = 0, sD = 0;
        if (deg > 0) { int s0 = __ldcs(sp);     eaA = __ldcs(ep);     aA = __ldg(&xl4[s0 * 8 + lane]); }
        if (deg > 1) { int s1 = __ldcs(sp + 1); eaB = __ldcs(ep + 1); aB = __ldg(&xl4[s1 * 8 + lane]); }
        if (deg > 2) { sC = __ldcs(sp + 2); eaC = __ldcs(ep + 2); }
        if (deg > 3) { sD = __ldcs(sp + 3); eaD = __ldcs(ep + 3); }

        for (int j = 0; j < deg; j++) {
            float4 a = aA, ea = eaA;
            aA = aB; eaA = eaB;
            if (j + 2 < deg) { aB = __ldg(&xl4[sC * 8 + lane]); eaB = eaC; }
            sC = sD; eaC = eaD;
            if (j + 4 < deg) { sD = __ldcs(sp + j + 4); eaD = __ldcs(ep + j + 4); }

            float mx = a.x + xr.x + ea.x * w0.x + ea.y * w1.x + ea.z * w2.x + ea.w * w3.x;
            float my = a.y + xr.y + ea.x * w0.y + ea.y * w1.y + ea.z * w2.y + ea.w * w3.y;
            float mz = a.z + xr.z + ea.x * w0.z + ea.y * w1.z + ea.z * w2.z + ea.w * w3.z;
            float mw = a.w + xr.w + ea.x * w0.w + ea.y * w1.w + ea.z * w2.w + ea.w * w3.w;
            float pe = leaky(mx) * at.x + leaky(my) * at.y + leaky(mz) * at.z + leaky(mw) * at.w;
            pe += __shfl_xor_sync(smask, pe, 1);
            pe += __shfl_xor_sync(smask, pe, 2);
            float exe = __expf(pe);
            den += exe;
            acc.x += exe * a.x; acc.y += exe * a.y;
            acc.z += exe * a.z; acc.w += exe * a.w;
        }
        float inv = 1.f / den;
        float4 gb = sGb[lane];
        float rx = acc.x * inv + gb.x;
        float ry = acc.y * inv + gb.y;
        float rz = acc.z * inv + gb.z;
        float rw = acc.w * inv + gb.w;
        ((float4*)d_g)[n * 8 + lane] = make_float4(rx, ry, rz, rw);
        s_loc = rx + ry + rz + rw;
        q_loc = rx * rx + ry * ry + rz * rz + rw * rw;
    }
    blockReduceAdd2(s_loc, q_loc, &d_stats[0], &d_stats[1]);
}

// ------- K_lin: graph_LN(g)+relu, u = t @ linW + linb; accumulate norm2 stats ----
__global__ void __launch_bounds__(256) k_lin(
    const float* __restrict__ n1w, const float* __restrict__ n1b,
    const float* __restrict__ linW, const float* __restrict__ linb, int N)
{
    __shared__ float st[16][33];
    __shared__ float sW[512];
    __shared__ float sb[16];
    int t = threadIdx.x;
    int n0 = blockIdx.x * 16;
    for (int i = t; i < 512; i += 256) sW[i] = linW[i];
    if (t < 16) sb[t] = linb[t];

    double mu_d  = d_stats[0] / (32.0 * N);
    double var_d = d_stats[1] / (32.0 * N) - mu_d * mu_d;
    float mu  = (float)mu_d;
    float inv = rsqrtf((float)var_d + EPSV);

#pragma unroll
    for (int r = 0; r < 2; r++) {
        int i = t + r * 256;
        int nl = i >> 5, k = i & 31;
        int gn = n0 + nl;
        float v = 0.f;
        if (gn < N) {
            v = (d_g[gn * 32 + k] - mu) * inv * n1w[k] + n1b[k];
            v = fmaxf(v, 0.f);
        }
        st[nl][k] = v;
    }
    __syncthreads();

    int nl = t >> 4, c = t & 15;
    int gn = n0 + nl;
    float s_loc = 0.f, q_loc = 0.f;
    if (gn < N) {
        float acc = sb[c];
#pragma unroll
        for (int k = 0; k < 32; k++) acc += st[nl][k] * sW[k * 16 + c];
        d_u[gn * 16 + c] = acc;
        s_loc = acc;
        q_loc = acc * acc;
    }
    blockReduceAdd2(s_loc, q_loc, &d_stats[2], &d_stats[3]);
}

// ------- K_resid_tf: graph_LN(u)+resid+relu -> h; out=max; next-layer xl/xr ------
__global__ void __launch_bounds__(256) k_resid_tf(
    const float* __restrict__ n2w, const float* __restrict__ n2b,
    const float* __restrict__ Wl, const float* __restrict__ bl,
    const float* __restrict__ Wr, const float* __restrict__ br,
    float* __restrict__ out, int N)
{
    __shared__ float sh[64][17];
    __shared__ float sWl[512], sWr[512], sbl[32], sbr[32];
    int t = threadIdx.x;
    int n0 = blockIdx.x * 64;
    if (blockIdx.x == 0 && t >= 128 && t < 130) d_stats[t - 128] = 0.0;
    for (int i = t; i < 512; i += 256) { sWl[i] = Wl[i]; sWr[i] = Wr[i]; }
    if (t < 32) { sbl[t] = bl[t]; sbr[t] = br[t]; }

    double mu_d  = d_stats[2] / (16.0 * N);
    double var_d = d_stats[3] / (16.0 * N) - mu_d * mu_d;
    float mu  = (float)mu_d;
    float inv = rsqrtf((float)var_d + EPSV);

#pragma unroll
    for (int r = 0; r < 4; r++) {
        int li = t + r * 256;
        int nl = li >> 4, c = li & 15;
        int gn = n0 + nl;
        float hn = 0.f;
        if (gn < N) {
            int i = gn * 16 + c;
            float v = (d_u[i] - mu) * inv * n2w[c] + n2b[c];
            hn = fmaxf(v + d_h[i], 0.f);
            d_h[i] = hn;
            out[i] = fmaxf(out[i], hn);
        }
        sh[nl][c] = hn;
    }
    __syncthreads();

    int c = t & 31, w = t >> 5;
#pragma unroll
    for (int j = 0; j < 8; j++) {
        int nl = w * 8 + j;
        int gn = n0 + nl;
        if (gn >= N) break;   // warp-uniform
        float al = sbl[c], ar = sbr[c];
#pragma unroll
        for (int k = 0; k < 16; k++) {
            float hv = sh[nl][k];
            al += hv * sWl[k * 32 + c];
            ar += hv * sWr[k * 32 + c];
        }
        d_xl[gn * 32 + c] = al;
        d_xr[gn * 32 + c] = ar;
    }
}

// ------- K_resid (last layer): graph_LN(u)+resid+relu; out = max(out, h) ---------
__global__ void __launch_bounds__(256) k_resid(
    const float* __restrict__ n2w, const float* __restrict__ n2b,
    float* __restrict__ out, int N)
{
    int i = blockIdx.x * 256 + threadIdx.x;
    if (i >= N * 16) return;
    int c = i & 15;
    double mu_d  = d_stats[2] / (16.0 * N);
    double var_d = d_stats[3] / (16.0 * N) - mu_d * mu_d;
    float mu  = (float)mu_d;
    float inv = rsqrtf((float)var_d + EPSV);
    float v  = (d_u[i] - mu) * inv * n2w[c] + n2b[c];
    float hn = fmaxf(v + d_h[i], 0.f);
    out[i] = fmaxf(out[i], hn);
}

// ---------------- launch ----------------
extern "C" void kernel_launch(void* const* d_in, const int* in_sizes, int n_in,
                              void* d_out, int out_size)
{
    const float* x     = (const float*)d_in[0];
    const int*   ei32  = (const int*)d_in[1];
    const float* eattr = (const float*)d_in[2];
    const float* embW  = (const float*)d_in[3];
    const float* embB  = (const float*)d_in[4];
    const float* ln0w  = (const float*)d_in[5];
    const float* ln0b  = (const float*)d_in[6];
    const float* Wl    = (const float*)d_in[7];
    const float* bl    = (const float*)d_in[8];
    const float* Wr    = (const float*)d_in[9];
    const float* br    = (const float*)d_in[10];
    const float* We    = (const float*)d_in[11];
    const float* att   = (const float*)d_in[12];
    const float* gatb  = (const float*)d_in[13];
    const float* n1w   = (const float*)d_in[14];
    const float* n1b   = (const float*)d_in[15];
    const float* linW  = (const float*)d_in[16];
    const float* linb  = (const float*)d_in[17];
    const float* n2w   = (const float*)d_in[18];
    const float* n2b   = (const float*)d_in[19];
    float* out = (float*)d_out;

    int N  = in_sizes[0] / 128;
    int E  = in_sizes[2] / 4;            // edge_attr is (E, 4)
    int NB = (N + PB - 1) / PB;          // 196 for N=100000 (co-resident)

    k_conv    <<<(E + 255) / 256, 256>>>(ei32, E, N);                 // 1
    k_prep    <<<NB, PB>>>((const float4*)eattr, E, N, NB);           // 2
    k_embed_tf<<<(N + 31) / 32, 256>>>(x, embW, embB, ln0w, ln0b,
                                       Wl, bl, Wr, br, out, N);       // 3

    for (int l = 0; l < 2; l++) {
        k_edge_csr<<<(N * 8 + 255) / 256, 256>>>(We + l * 128, att + l * 32,
                                                 gatb + l * 32, N, l == 1);  // 4 (ncu), 7
        k_lin<<<(N + 15) / 16, 256>>>(n1w + l * 32, n1b + l * 32,
                                      linW + l * 512, linb + l * 16, N);     // 5, 8
        if (l == 0) {
            k_resid_tf<<<(N + 63) / 64, 256>>>(n2w, n2b,
                                               Wl + 512, bl + 32, Wr + 512, br + 32,
                                               out, N);                      // 6
        } else {
            k_resid<<<(N * 16 + 255) / 256, 256>>>(n2w + 16, n2b + 16, out, N); // 9
        }
    }
}